// round 9
// baseline (speedup 1.0000x reference)
#include <cuda_runtime.h>
#include <cfloat>

#define Nn 20000
#define Ee 320000
#define Gg 64
#define D0 16
#define Hh 32
#define NK 33
#define EPSI 1e-5f
#define FULL 0xffffffffu
#define EDGE_BLKS ((Ee+255)/256)      /* 1250 */
#define AGG_BLKS  (Nn/8)              /* 2500 (general-path PQ grids) */
#define AGG_GRID  888                 /* persistent agg: 6 blocks/SM */

// ---------------- static device scratch (zero-init at load; self-cleaning across replays) ----------------
__device__ float g_A0[NK*D0*Hh], g_B0[NK*D0*Hh];
__device__ float g_A1[NK*Hh*Hh], g_B1[NK*Hh*Hh];
__device__ unsigned char g_k0[Ee], g_k1[Ee];
__device__ int g_hist[2*NK];            // zeroed by k_mlp each run
__device__ int g_deg[Nn];               // zeroed by k_alloc after read
__device__ int g_total;                 // zeroed by k_mlp each run
__device__ int g_off[Nn], g_end[Nn], g_cur[Nn];
__device__ int g_nlive[2], g_klive[2];
__device__ uint2 g_ebuf[Ee];            // CSR-ordered packed payload
__device__ __align__(16) float g_PQ[(size_t)NK*Nn*64];   // general path only
__device__ __align__(16) float g_h[Nn*Hh], g_hn[Nn*Hh];
__device__ float g_stats[4*Hh];         // [sum0|sq0|sum1|sq1], zeroed by k_pre block 0
__device__ float g_pool[Gg*Hh];
__device__ int   g_pcnt[Gg];

__device__ __forceinline__ void rank32(float wj, float bj, float& t, int& r, int j){
    t = (wj != 0.0f) ? (-bj / wj) : FLT_MAX;
    r = 0;
    #pragma unroll
    for (int m = 0; m < 32; m++){
        float tm = __shfl_sync(FULL, t, m);
        r += (tm < t || (tm == t && m < j));
    }
}

// component-static broadcast of float4 element i%4 from lane i/4
#define BCAST4(vec, i) __shfl_sync(FULL, ((i)&3)==0 ? (vec).x : ((i)&3)==1 ? (vec).y : ((i)&3)==2 ? (vec).z : (vec).w, (i)>>2)

// ==== fused: blocks [0,2*NK) buildAB, blocks [2*NK,...) per-edge interval/hist/deg ====
__global__ void __launch_bounds__(256)
k_pre(const float* attr, const int* dst,
      const float* ew1a, const float* eb1a, const float* ew2a, const float* eb2a,
      const float* ew1b, const float* eb1b, const float* ew2b, const float* eb2b){
    int t = threadIdx.x;
    if (blockIdx.x < 2*NK){
        if (blockIdx.x == 0){
            for (int i = t; i < 4*Hh; i += 256) g_stats[i] = 0.f;
            for (int i = t; i < Gg*Hh; i += 256) g_pool[i] = 0.f;
            if (t < Gg) g_pcnt[t] = 0;
        }
        int layer = (blockIdx.x >= NK);
        int k = blockIdx.x - layer*NK;
        int D = layer ? (Hh*Hh) : (D0*Hh);
        float* A = layer ? g_A1 : g_A0;
        float* B = layer ? g_B1 : g_B0;
        const float* ew1 = layer ? ew1b : ew1a;
        const float* eb1 = layer ? eb1b : eb1a;
        const float* ew2 = layer ? ew2b : ew2a;
        const float* eb2 = layer ? eb2b : eb2a;
        __shared__ float sw[32], sb[32]; __shared__ int sr[32];
        if (t < 32){
            float wj = ew1[t], bj = eb1[t], tv; int r;
            rank32(wj, bj, tv, r, t);
            sw[t]=wj; sb[t]=bj; sr[t]=r;
        }
        __syncthreads();
        for (int d = t; d < D; d += 256){
            float a = 0.f, b = eb2[d];
            for (int j=0;j<32;j++){
                float wj = sw[j];
                bool act = (wj > 0.f) ? (k > sr[j]) : ((wj < 0.f) ? (k <= sr[j]) : (sb[j] > 0.f));
                if (act){ float w2 = ew2[j*D+d]; a += wj*w2; b += sb[j]*w2; }
            }
            A[k*D+d]=a; B[k*D+d]=b;
        }
        return;
    }
    // ---- edge role ----
    __shared__ float st0[32], st1[32];
    __shared__ int sh[2*NK];
    int lane = t & 31;
    if (t < 32){ float tv; int r; rank32(ew1a[t], eb1a[t], tv, r, t); st0[r]=tv; }
    else if (t < 64){ int j=t-32; float tv; int r; rank32(ew1b[j], eb1b[j], tv, r, j); st1[r]=tv; }
    if (t < 2*NK) sh[t] = 0;
    __syncthreads();
    int e = (blockIdx.x - 2*NK)*256 + t;
    bool valid = (e < Ee);
    float a = valid ? attr[e] : -FLT_MAX;
    int k0 = 0, k1 = 0;
    #pragma unroll
    for (int step = 16; step > 0; step >>= 1){
        if (st0[k0 + step - 1] <= a) k0 += step;
        if (st1[k1 + step - 1] <= a) k1 += step;
    }
    k0 += (st0[k0] <= a);   // counts range [0,32]
    k1 += (st1[k1] <= a);
    if (valid){
        g_k0[e]=(unsigned char)k0; g_k1[e]=(unsigned char)k1;
        atomicAdd(&g_deg[dst[e]],1);
    }
    int key0 = valid ? k0 : -1;
    unsigned m0 = __match_any_sync(FULL, key0);
    if (valid && lane == (__ffs(m0)-1)) atomicAdd(&sh[k0], __popc(m0));
    int key1 = valid ? k1 : -1;
    unsigned m1 = __match_any_sync(FULL, key1);
    if (valid && lane == (__ffs(m1)-1)) atomicAdd(&sh[NK+k1], __popc(m1));
    __syncthreads();
    if (t < 2*NK && sh[t]) atomicAdd(&g_hist[t], sh[t]);
}

// ==== segment allocation: warp-aggregated atomic bump; order-free CSR. Also nlive detect. ====
__global__ void __launch_bounds__(256)
k_alloc(){
    int i = blockIdx.x*256 + threadIdx.x;
    int lane = threadIdx.x & 31;
    if (blockIdx.x == 0 && threadIdx.x < 2){
        int base = threadIdx.x*NK, n = 0, kl = 0;
        for (int k = 0; k < NK; k++) if (g_hist[base+k] > 0){ n++; kl = k; }
        g_nlive[threadIdx.x] = n; g_klive[threadIdx.x] = kl;
    }
    int d = (i < Nn) ? g_deg[i] : 0;
    int sc = d;
    #pragma unroll
    for (int off = 1; off < 32; off <<= 1){
        int y = __shfl_up_sync(FULL, sc, off);
        if (lane >= off) sc += y;
    }
    int tot = __shfl_sync(FULL, sc, 31);
    int base = 0;
    if (lane == 31 && tot) base = atomicAdd(&g_total, tot);
    base = __shfl_sync(FULL, base, 31);
    if (i < Nn){
        int my = base + sc - d;
        g_off[i] = my; g_cur[i] = my; g_end[i] = my + d;
        g_deg[i] = 0;
    }
}

// ==== fused: blocks [0,EDGE_BLKS) CSR fill; blocks [EDGE_BLKS,..) PQ layer 0 (general only) ====
__global__ void __launch_bounds__(256)
k_fillPQ(const int* dst, const int* src, const float* attr, const float* xin){
    if (blockIdx.x < EDGE_BLKS){
        bool fastboth = (g_nlive[0] == 1) & (g_nlive[1] == 1);
        int e = blockIdx.x*256 + threadIdx.x;
        if (e < Ee){
            unsigned px = (unsigned)src[e];
            if (!fastboth)
                px |= ((unsigned)g_k0[e] << 16) | ((unsigned)g_k1[e] << 24);
            uint2 pl; pl.x = px; pl.y = __float_as_uint(attr[e]);
            int p = atomicAdd(&g_cur[dst[e]], 1);
            g_ebuf[p] = pl;
        }
        return;
    }
    if (g_nlive[0] == 1) return;     // fast path: PQ not needed
    int lane = threadIdx.x & 31;
    int u = (blockIdx.x - EDGE_BLKS)*8 + (threadIdx.x >> 5);
    if (u >= Nn) return;
    float xv_l = (lane < D0) ? __ldg(xin + (size_t)u*D0 + lane) : 0.f;
    for (int k = 0; k < NK; k++){
        if (g_hist[k] == 0) continue;
        float p = 0.f, q = 0.f;
        for (int i = 0; i < D0; i++){
            float xv = __shfl_sync(FULL, xv_l, i);
            p = fmaf(xv, __ldg(g_A0 + k*D0*Hh + i*Hh + lane), p);
            q = fmaf(xv, __ldg(g_B0 + k*D0*Hh + i*Hh + lane), q);
        }
        size_t ro = ((size_t)(k*Nn + u))*64;
        g_PQ[ro + lane] = p;
        g_PQ[ro + 32 + lane] = q;
    }
}

// ==== PQ layer 1 (general path only; BN+ReLU inline from layer-0 stats) ====
__global__ void __launch_bounds__(256)
k_PQ1(const float* gamma, const float* beta){
    if (g_nlive[1] == 1) return;
    int lane = threadIdx.x & 31;
    int u = blockIdx.x*8 + (threadIdx.x >> 5);
    if (u >= Nn) return;
    float mu  = g_stats[lane]    * (1.f/(float)Nn);
    float var = g_stats[32+lane] * (1.f/(float)Nn) - mu*mu;
    float sc  = rsqrtf(var + EPSI) * __ldg(gamma+lane);
    float shf = __ldg(beta+lane) - mu*sc;
    float xv_l = fmaxf(g_h[(size_t)u*32 + lane]*sc + shf, 0.f);
    for (int k = 0; k < NK; k++){
        if (g_hist[NK + k] == 0) continue;
        float p = 0.f, q = 0.f;
        for (int i = 0; i < Hh; i++){
            float xv = __shfl_sync(FULL, xv_l, i);
            p = fmaf(xv, __ldg(g_A1 + k*Hh*Hh + i*Hh + lane), p);
            q = fmaf(xv, __ldg(g_B1 + k*Hh*Hh + i*Hh + lane), q);
        }
        size_t ro = ((size_t)(k*Nn + u))*64;
        g_PQ[ro + lane] = p;
        g_PQ[ro + 32 + lane] = q;
    }
}

// ==== PERSISTENT aggregation: 888 blocks (6/SM); warps stride nodes; shuffle epilogue ====
template<int DIN, int LAYER>
__global__ void __launch_bounds__(256, 6)
k_agg(const float* __restrict__ xin, const float* __restrict__ root,
      const float* __restrict__ bias, const float* __restrict__ gamma0,
      const float* __restrict__ beta0, float* __restrict__ hout){
    constexpr int NC = DIN/4;        // float4 chunks per x row
    constexpr int NS = 32/NC;        // edge slots per stream
    __shared__ float sA[DIN*32], sB[DIN*32], sR[DIN*32];
    __shared__ float sScale[32], sShift[32], sBias[32];
    __shared__ float sAcc[8][32];
    __shared__ float ss[32], sq[32];
    int t = threadIdx.x, lane = t & 31, w = t >> 5;
    int nlive = g_nlive[LAYER];
    int kl = g_klive[LAYER];
    if (t < 32){ ss[t] = 0.f; sq[t] = 0.f; sBias[t] = __ldg(bias+t); }
    if (LAYER == 1 && t < 32){
        float mu  = g_stats[t]    * (1.f/(float)Nn);
        float var = g_stats[32+t] * (1.f/(float)Nn) - mu*mu;
        float sc  = rsqrtf(var + EPSI) * __ldg(gamma0+t);
        sScale[t] = sc;
        sShift[t] = __ldg(beta0+t) - mu*sc;
    }
    for (int d = t; d < DIN*32; d += 256) sR[d] = __ldg(root + d);
    if (nlive == 1){
        const float* A = LAYER ? g_A1 : g_A0;
        const float* B = LAYER ? g_B1 : g_B0;
        for (int d = t; d < DIN*32; d += 256){
            sA[d] = __ldg(A + kl*DIN*32 + d);
            sB[d] = __ldg(B + kl*DIN*32 + d);
        }
    }
    __syncthreads();

    int slot, c;
    if (nlive == 1){ slot = lane / NC; c = lane % NC; }
    else           { slot = lane >> 3; c = lane & 7; }
    const float4* x4 = (const float4*)xin;

    for (int v = blockIdx.x*8 + w; v < Nn; v += AGG_GRID*8){
        int s = g_off[v], e1 = g_end[v];
        float msg;
        if (nlive == 1){
            // ---------- fast path: two pipelined streams, 2*NS edges in flight ----------
            float4 ya0={0,0,0,0}, yb0={0,0,0,0}, ya1={0,0,0,0}, yb1={0,0,0,0};
            int i0 = s + slot, i1 = i0 + NS;
            bool v0 = i0 < e1, v1 = i1 < e1;
            uint2 p0, p1;
            if (v0) p0 = g_ebuf[i0];
            if (v1) p1 = g_ebuf[i1];
            while (__any_sync(FULL, v0)){
                int n0 = i0 + 2*NS, n1 = i1 + 2*NS;
                bool w0 = n0 < e1, w1 = n1 < e1;
                uint2 q0, q1;
                if (w0) q0 = g_ebuf[n0];
                if (w1) q1 = g_ebuf[n1];
                if (v0){
                    int u = p0.x & 0xFFFF; float a = __uint_as_float(p0.y);
                    float4 xc = x4[(size_t)u*NC + c];
                    if (LAYER == 1){
                        int f = c*4;
                        xc.x = fmaxf(xc.x*sScale[f+0] + sShift[f+0], 0.f);
                        xc.y = fmaxf(xc.y*sScale[f+1] + sShift[f+1], 0.f);
                        xc.z = fmaxf(xc.z*sScale[f+2] + sShift[f+2], 0.f);
                        xc.w = fmaxf(xc.w*sScale[f+3] + sShift[f+3], 0.f);
                    }
                    ya0.x = fmaf(a, xc.x, ya0.x); yb0.x += xc.x;
                    ya0.y = fmaf(a, xc.y, ya0.y); yb0.y += xc.y;
                    ya0.z = fmaf(a, xc.z, ya0.z); yb0.z += xc.z;
                    ya0.w = fmaf(a, xc.w, ya0.w); yb0.w += xc.w;
                }
                if (v1){
                    int u = p1.x & 0xFFFF; float a = __uint_as_float(p1.y);
                    float4 xc = x4[(size_t)u*NC + c];
                    if (LAYER == 1){
                        int f = c*4;
                        xc.x = fmaxf(xc.x*sScale[f+0] + sShift[f+0], 0.f);
                        xc.y = fmaxf(xc.y*sScale[f+1] + sShift[f+1], 0.f);
                        xc.z = fmaxf(xc.z*sScale[f+2] + sShift[f+2], 0.f);
                        xc.w = fmaxf(xc.w*sScale[f+3] + sShift[f+3], 0.f);
                    }
                    ya1.x = fmaf(a, xc.x, ya1.x); yb1.x += xc.x;
                    ya1.y = fmaf(a, xc.y, ya1.y); yb1.y += xc.y;
                    ya1.z = fmaf(a, xc.z, ya1.z); yb1.z += xc.z;
                    ya1.w = fmaf(a, xc.w, ya1.w); yb1.w += xc.w;
                }
                i0 = n0; i1 = n1; v0 = w0; v1 = w1; p0 = q0; p1 = q1;
            }
            float4 ya, yb;
            ya.x = ya0.x + ya1.x; ya.y = ya0.y + ya1.y;
            ya.z = ya0.z + ya1.z; ya.w = ya0.w + ya1.w;
            yb.x = yb0.x + yb1.x; yb.y = yb0.y + yb1.y;
            yb.z = yb0.z + yb1.z; yb.w = yb0.w + yb1.w;
            #pragma unroll
            for (int off = NC; off < 32; off <<= 1){
                ya.x += __shfl_xor_sync(FULL, ya.x, off);
                ya.y += __shfl_xor_sync(FULL, ya.y, off);
                ya.z += __shfl_xor_sync(FULL, ya.z, off);
                ya.w += __shfl_xor_sync(FULL, ya.w, off);
                yb.x += __shfl_xor_sync(FULL, yb.x, off);
                yb.y += __shfl_xor_sync(FULL, yb.y, off);
                yb.z += __shfl_xor_sync(FULL, yb.z, off);
                yb.w += __shfl_xor_sync(FULL, yb.w, off);
            }
            // all lanes now hold their chunk's total; broadcast via static-component shuffle
            msg = 0.f;
            #pragma unroll
            for (int i = 0; i < DIN; i++){
                float yai = BCAST4(ya, i);
                float ybi = BCAST4(yb, i);
                msg = fmaf(yai, sA[i*32+lane], msg);
                msg = fmaf(ybi, sB[i*32+lane], msg);
            }
        } else {
            // ---------- general path: gather P/Q rows ----------
            int shift = 16 + (LAYER << 3);
            float4 acc = {0,0,0,0};
            for (int base = s; base < e1; base += 4){
                int i = base + slot;
                if (i < e1){
                    uint2 pl = g_ebuf[i];
                    int u = pl.x & 0xFFFF; int kk = (pl.x >> shift) & 0xFF;
                    float a = __uint_as_float(pl.y);
                    const float4* row = (const float4*)(g_PQ + ((size_t)(kk*Nn + u))*64);
                    float4 p = row[c], q = row[8+c];
                    acc.x = fmaf(a, p.x, acc.x) + q.x;
                    acc.y = fmaf(a, p.y, acc.y) + q.y;
                    acc.z = fmaf(a, p.z, acc.z) + q.z;
                    acc.w = fmaf(a, p.w, acc.w) + q.w;
                }
            }
            #pragma unroll
            for (int off = 8; off < 32; off <<= 1){
                acc.x += __shfl_xor_sync(FULL, acc.x, off);
                acc.y += __shfl_xor_sync(FULL, acc.y, off);
                acc.z += __shfl_xor_sync(FULL, acc.z, off);
                acc.w += __shfl_xor_sync(FULL, acc.w, off);
            }
            if (lane < 8){
                int f = lane*4;
                sAcc[w][f+0] = acc.x; sAcc[w][f+1] = acc.y;
                sAcc[w][f+2] = acc.z; sAcc[w][f+3] = acc.w;
            }
            __syncwarp();
            msg = sAcc[w][lane];
        }

        // ---------- epilogue for this node ----------
        float inv = 1.f / fmaxf((float)(e1 - s), 1.f);
        float xv = 0.f;
        if (lane < DIN){
            xv = __ldg(xin + (size_t)v*DIN + lane);
            if (LAYER == 1) xv = fmaxf(xv*sScale[lane] + sShift[lane], 0.f);
        }
        float rt = 0.f;
        #pragma unroll
        for (int i = 0; i < DIN; i++)
            rt = fmaf(__shfl_sync(FULL, xv, i), sR[i*32+lane], rt);
        float o = rt + msg*inv + sBias[lane];
        hout[(size_t)v*32 + lane] = o;
        atomicAdd(&ss[lane], o);
        atomicAdd(&sq[lane], o*o);
    }
    __syncthreads();
    if (t < 32){
        atomicAdd(&g_stats[LAYER*64 + t],      ss[t]);
        atomicAdd(&g_stats[LAYER*64 + 32 + t], sq[t]);
    }
}

// ==== BN2 + ReLU + pooling (layer-1 stats) ====
__global__ void __launch_bounds__(256)
k_apply1(const float* h2, const float* gamma, const float* beta, const int* batch){
    int idx = blockIdx.x*blockDim.x + threadIdx.x;
    if (idx >= Nn*Hh) return;
    int f = idx & 31, v = idx >> 5;
    float mu  = g_stats[64+f] * (1.f/(float)Nn);
    float var = g_stats[96+f] * (1.f/(float)Nn) - mu*mu;
    float sc  = rsqrtf(var + EPSI) * __ldg(gamma+f);
    float xv = fmaxf((h2[idx] - mu)*sc + __ldg(beta+f), 0.f);
    int g = batch[v];
    atomicAdd(&g_pool[g*Hh + f], xv);
    if (f == 0) atomicAdd(&g_pcnt[g], 1);
}

// ==== readout MLP; self-cleans g_hist + g_total ====
__global__ void __launch_bounds__(64)
k_mlp(const float* edft, const float* w1, const float* b1,
      const float* w2, const float* b2, float* out){
    int g = threadIdx.x;
    g_hist[g] = 0;
    if (g < 2*NK - 64) g_hist[64 + g] = 0;
    if (g == 0) g_total = 0;
    if (g >= Gg) return;
    float zin[Hh+1];
    float inv = 1.f / fmaxf((float)g_pcnt[g], 1.f);
    for (int i = 0; i < Hh; i++) zin[i] = g_pool[g*Hh+i]*inv;
    zin[Hh] = edft[g];
    float o = b2[0];
    for (int j = 0; j < 64; j++){
        float hsum = b1[j];
        #pragma unroll
        for (int i = 0; i < Hh+1; i++) hsum = fmaf(zin[i], w1[i*64+j], hsum);
        o = fmaf(fmaxf(hsum, 0.f), w2[j], o);
    }
    out[g] = o;
}

extern "C" void kernel_launch(void* const* d_in, const int* in_sizes, int n_in,
                              void* d_out, int out_size){
    const float* x     = (const float*)d_in[0];
    const float* attr  = (const float*)d_in[1];
    const float* edft  = (const float*)d_in[2];
    const int*   src   = (const int*)  d_in[3];
    const int*   dst   = (const int*)  d_in[4];
    const int*   batch = (const int*)  d_in[5];
    const float* l0w1=(const float*)d_in[6],  *l0b1=(const float*)d_in[7];
    const float* l0w2=(const float*)d_in[8],  *l0b2=(const float*)d_in[9];
    const float* l0root=(const float*)d_in[10],*l0bias=(const float*)d_in[11];
    const float* l0g=(const float*)d_in[12],  *l0be=(const float*)d_in[13];
    const float* l1w1=(const float*)d_in[14], *l1b1=(const float*)d_in[15];
    const float* l1w2=(const float*)d_in[16], *l1b2=(const float*)d_in[17];
    const float* l1root=(const float*)d_in[18],*l1bias=(const float*)d_in[19];
    const float* l1g=(const float*)d_in[20],  *l1be=(const float*)d_in[21];
    const float* mw1=(const float*)d_in[22],  *mb1=(const float*)d_in[23];
    const float* mw2=(const float*)d_in[24],  *mb2=(const float*)d_in[25];
    float* out = (float*)d_out;

    void *pH, *pHn;
    cudaGetSymbolAddress(&pH,  g_h);
    cudaGetSymbolAddress(&pHn, g_hn);
    float* h  = (float*)pH;
    float* h2 = (float*)pHn;

    k_pre<<<2*NK + EDGE_BLKS, 256>>>(attr, dst,
                                     l0w1,l0b1,l0w2,l0b2, l1w1,l1b1,l1w2,l1b2);
    k_alloc<<<(Nn+255)/256,256>>>();
    k_fillPQ<<<EDGE_BLKS + AGG_BLKS, 256>>>(dst, src, attr, x);

    k_agg<D0,0><<<AGG_GRID,256>>>(x, l0root, l0bias, l0g, l0be, h);
    k_PQ1<<<AGG_BLKS,256>>>(l0g, l0be);
    k_agg<Hh,1><<<AGG_GRID,256>>>(h, l1root, l1bias, l0g, l0be, h2);
    k_apply1<<<(Nn*Hh+255)/256,256>>>(h2, l1g, l1be, batch);
    k_mlp<<<1,64>>>(edft, mw1, mb1, mw2, mb2, out);
}